// round 5
// baseline (speedup 1.0000x reference)
#include <cuda_runtime.h>
#include <stdint.h>

#define N_NODES_MAX 100000
#define N_EDGES_MAX 400000
#define DIM 128
#define AS_LD 132
#define WS_LD 136
// A tile 128 x AS_LD + two weight tiles 128 x WS_LD (all 4B words)
#define SMEM_WORDS (128 * AS_LD + 2 * 128 * WS_LD)
#define SMEM_BYTES (SMEM_WORDS * 4)

// ---------------- scratch (device globals; no allocation allowed) ----------
__device__ int   g_deg[N_NODES_MAX];
__device__ int   g_off[N_NODES_MAX];
__device__ int   g_cur[N_NODES_MAX];
__device__ int   g_srcs[N_EDGES_MAX];
__device__ int   g_bsum[128];
__device__ float g_sum[DIM];
__device__ float g_sumsq[DIM];
__device__ float g_scale[DIM];
__device__ float g_shift[DIM];
__device__ unsigned g_w1t[128 * WS_LD];
__device__ unsigned g_w2t[128 * WS_LD];

__device__ __forceinline__ unsigned f2tf32(float f) {
    unsigned u;
    asm("cvt.rna.tf32.f32 %0, %1;" : "=r"(u) : "f"(f));
    return u;
}

__device__ __forceinline__ void mma_tf32(float c[4], unsigned a0, unsigned a1,
                                         unsigned a2, unsigned a3,
                                         unsigned b0, unsigned b1) {
    asm volatile(
        "mma.sync.aligned.m16n8k8.row.col.f32.tf32.tf32.f32 "
        "{%0,%1,%2,%3}, {%4,%5,%6,%7}, {%8,%9}, {%0,%1,%2,%3};"
        : "+f"(c[0]), "+f"(c[1]), "+f"(c[2]), "+f"(c[3])
        : "r"(a0), "r"(a1), "r"(a2), "r"(a3), "r"(b0), "r"(b1));
}

// K0: zero degree counters & BN accumulators; build transposed tf32 weights
__global__ void k_prep(const float* __restrict__ w1, const float* __restrict__ w2, int n) {
    int i = blockIdx.x * blockDim.x + threadIdx.x;
    if (i < n) g_deg[i] = 0;
    if (i < DIM) { g_sum[i] = 0.f; g_sumsq[i] = 0.f; }
    if (i < 128 * WS_LD) {
        int k = i / WS_LD, c = i % WS_LD;
        unsigned v1 = 0, v2 = 0;
        if (c < 128) { v1 = f2tf32(w1[c * 128 + k]); v2 = f2tf32(w2[c * 128 + k]); }
        g_w1t[i] = v1;
        g_w2t[i] = v2;
    }
}

// K1: histogram of in-degrees (edge_index int32 [2][E])
__global__ void k_hist(const int* __restrict__ ei, int e, int n) {
    int i = blockIdx.x * blockDim.x + threadIdx.x;
    if (i < e) {
        int d = __ldg(ei + e + i);
        if ((unsigned)d < (unsigned)n) atomicAdd(&g_deg[d], 1);
    }
}

// K2: exclusive scan, 2048 elements per 512-thread block (shuffle-based)
__global__ void k_scan1(int n) {
    __shared__ int wsum[16];
    int t = threadIdx.x;
    int base = blockIdx.x * 2048 + t * 4;
    int v0 = 0, v1 = 0, v2 = 0, v3 = 0;
    if (base + 3 < n) {
        int4 q = *(const int4*)(g_deg + base);
        v0 = q.x; v1 = q.y; v2 = q.z; v3 = q.w;
    } else {
        if (base + 0 < n) v0 = g_deg[base + 0];
        if (base + 1 < n) v1 = g_deg[base + 1];
        if (base + 2 < n) v2 = g_deg[base + 2];
        if (base + 3 < n) v3 = g_deg[base + 3];
    }
    int tsum = v0 + v1 + v2 + v3;
    int lane = t & 31, w = t >> 5;
    int incl = tsum;
#pragma unroll
    for (int o = 1; o < 32; o <<= 1) {
        int x = __shfl_up_sync(~0u, incl, o);
        if (lane >= o) incl += x;
    }
    if (lane == 31) wsum[w] = incl;
    __syncthreads();
    if (t < 16) {
        int s = wsum[t];
        int i2 = s;
#pragma unroll
        for (int o = 1; o < 16; o <<= 1) {
            int x = __shfl_up_sync(0xffffu, i2, o);
            if (t >= o) i2 += x;
        }
        wsum[t] = i2 - s;
        if (t == 15) g_bsum[blockIdx.x] = i2;
    }
    __syncthreads();
    int run = incl - tsum + wsum[w];
    if (base + 0 < n) g_off[base + 0] = run; run += v0;
    if (base + 1 < n) g_off[base + 1] = run; run += v1;
    if (base + 2 < n) g_off[base + 2] = run; run += v2;
    if (base + 3 < n) g_off[base + 3] = run;
}

// K3: scan block sums (nb <= 64) in one warp
__global__ void k_scan2(int nb) {
    int t = threadIdx.x;  // 32
    int v0 = (2 * t < nb) ? g_bsum[2 * t] : 0;
    int v1 = (2 * t + 1 < nb) ? g_bsum[2 * t + 1] : 0;
    int s = v0 + v1, incl = s;
#pragma unroll
    for (int o = 1; o < 32; o <<= 1) {
        int x = __shfl_up_sync(~0u, incl, o);
        if (t >= o) incl += x;
    }
    int excl = incl - s;
    if (2 * t < nb) g_bsum[2 * t] = excl;
    if (2 * t + 1 < nb) g_bsum[2 * t + 1] = excl + v0;
}

// K4: add block offsets; init cursors
__global__ void k_scan3(int n) {
    int i = blockIdx.x * blockDim.x + threadIdx.x;
    if (i < n) {
        int o = g_off[i] + g_bsum[i >> 11];
        g_off[i] = o;
        g_cur[i] = o;
    }
}

// K5: scatter src indices into CSR
__global__ void k_scatter(const int* __restrict__ ei, int e, int n) {
    int i = blockIdx.x * blockDim.x + threadIdx.x;
    if (i < e) {
        int d = ei[e + i];
        int s = ei[i];
        if ((unsigned)d < (unsigned)n && (unsigned)s < (unsigned)n) {
            int p = atomicAdd(&g_cur[d], 1);
            if ((unsigned)p < (unsigned)N_EDGES_MAX) g_srcs[p] = s;
        }
    }
}

// K6: persistent fused kernel: CSR gather-agg -> MLP layer1(ReLU) -> layer2(ReLU)
//     -> out store (pre-BN) + BN column partial sums (register-accumulated).
__global__ void __launch_bounds__(512, 1)
k_gemm(const float* __restrict__ x,
       const float* __restrict__ b1, const float* __restrict__ b2,
       float* __restrict__ out, int M, int ntiles) {
    extern __shared__ unsigned sm[];
    unsigned* As = sm;                       // 128 x AS_LD
    unsigned* W1s = sm + 128 * AS_LD;        // 128 x WS_LD
    unsigned* W2s = W1s + 128 * WS_LD;       // 128 x WS_LD
    float* Asf = (float*)As;

    const int t = threadIdx.x;
    const int lane = t & 31, wid = t >> 5;
    const int g = lane >> 2, tig = lane & 3;
    const int mi = wid & 3;   // 4 row-blocks of 32
    const int nq = wid >> 2;  // 4 col-blocks of 32
    const int col = t & 127, quarter = t >> 7;

    // one-time weight load (both matrices resident)
    for (int i = t; i < 128 * WS_LD; i += 512) {
        W1s[i] = g_w1t[i];
        W2s[i] = g_w2t[i];
    }

    float bns = 0.f, bnss = 0.f;

    for (int tile = blockIdx.x; tile < ntiles; tile += gridDim.x) {
        const int row0 = tile * 128;
        __syncthreads();  // protect As reuse across loop iterations

        // ---- stage A: fused gather-aggregate, tf32 into As ----
#pragma unroll
        for (int rr = 0; rr < 8; rr++) {
            int r = wid * 8 + rr;
            int node = row0 + r;
            float4 acc = make_float4(0.f, 0.f, 0.f, 0.f);
            if (node < M) {
                acc = ((const float4*)(x + (size_t)node * DIM))[lane];
                int e = g_off[node];
                int end = e + g_deg[node];
                for (; e + 4 <= end; e += 4) {
                    int s0 = g_srcs[e], s1 = g_srcs[e + 1];
                    int s2 = g_srcs[e + 2], s3 = g_srcs[e + 3];
                    float4 v0 = ((const float4*)(x + (size_t)s0 * DIM))[lane];
                    float4 v1 = ((const float4*)(x + (size_t)s1 * DIM))[lane];
                    float4 v2 = ((const float4*)(x + (size_t)s2 * DIM))[lane];
                    float4 v3 = ((const float4*)(x + (size_t)s3 * DIM))[lane];
                    acc.x += v0.x + v1.x + v2.x + v3.x;
                    acc.y += v0.y + v1.y + v2.y + v3.y;
                    acc.z += v0.z + v1.z + v2.z + v3.z;
                    acc.w += v0.w + v1.w + v2.w + v3.w;
                }
                for (; e < end; e++) {
                    float4 v = ((const float4*)(x + (size_t)g_srcs[e] * DIM))[lane];
                    acc.x += v.x; acc.y += v.y; acc.z += v.z; acc.w += v.w;
                }
            }
            uint4 u = make_uint4(f2tf32(acc.x), f2tf32(acc.y), f2tf32(acc.z), f2tf32(acc.w));
            *(uint4*)(As + r * AS_LD + lane * 4) = u;
        }
        __syncthreads();

        float c[2][4][4];

        // ---------- layer 1 ----------
#pragma unroll
        for (int m = 0; m < 2; m++)
#pragma unroll
            for (int nt = 0; nt < 4; nt++)
#pragma unroll
                for (int j = 0; j < 4; j++) c[m][nt][j] = 0.f;

#pragma unroll 4
        for (int ks = 0; ks < 16; ks++) {
            int k0 = ks * 8;
            unsigned a[2][4];
#pragma unroll
            for (int m = 0; m < 2; m++) {
                int rb = mi * 32 + m * 16;
                a[m][0] = As[(rb + g) * AS_LD + k0 + tig];
                a[m][1] = As[(rb + g + 8) * AS_LD + k0 + tig];
                a[m][2] = As[(rb + g) * AS_LD + k0 + tig + 4];
                a[m][3] = As[(rb + g + 8) * AS_LD + k0 + tig + 4];
            }
#pragma unroll
            for (int nt = 0; nt < 4; nt++) {
                unsigned bb0 = W1s[(k0 + tig) * WS_LD + nq * 32 + nt * 8 + g];
                unsigned bb1 = W1s[(k0 + tig + 4) * WS_LD + nq * 32 + nt * 8 + g];
                mma_tf32(c[0][nt], a[0][0], a[0][1], a[0][2], a[0][3], bb0, bb1);
                mma_tf32(c[1][nt], a[1][0], a[1][1], a[1][2], a[1][3], bb0, bb1);
            }
        }
        __syncthreads();

        // epilogue 1: relu(c + b1) -> As (tf32)
#pragma unroll
        for (int m = 0; m < 2; m++)
#pragma unroll
            for (int nt = 0; nt < 4; nt++) {
                int cc = nq * 32 + nt * 8 + tig * 2;
                float bb0 = __ldg(b1 + cc), bb1v = __ldg(b1 + cc + 1);
                int r0l = mi * 32 + m * 16 + g;
                float v00 = fmaxf(c[m][nt][0] + bb0, 0.f);
                float v01 = fmaxf(c[m][nt][1] + bb1v, 0.f);
                float v10 = fmaxf(c[m][nt][2] + bb0, 0.f);
                float v11 = fmaxf(c[m][nt][3] + bb1v, 0.f);
                *(uint2*)(As + r0l * AS_LD + cc) = make_uint2(f2tf32(v00), f2tf32(v01));
                *(uint2*)(As + (r0l + 8) * AS_LD + cc) = make_uint2(f2tf32(v10), f2tf32(v11));
            }
        __syncthreads();

        // ---------- layer 2 ----------
#pragma unroll
        for (int m = 0; m < 2; m++)
#pragma unroll
            for (int nt = 0; nt < 4; nt++)
#pragma unroll
                for (int j = 0; j < 4; j++) c[m][nt][j] = 0.f;

#pragma unroll 4
        for (int ks = 0; ks < 16; ks++) {
            int k0 = ks * 8;
            unsigned a[2][4];
#pragma unroll
            for (int m = 0; m < 2; m++) {
                int rb = mi * 32 + m * 16;
                a[m][0] = As[(rb + g) * AS_LD + k0 + tig];
                a[m][1] = As[(rb + g + 8) * AS_LD + k0 + tig];
                a[m][2] = As[(rb + g) * AS_LD + k0 + tig + 4];
                a[m][3] = As[(rb + g + 8) * AS_LD + k0 + tig + 4];
            }
#pragma unroll
            for (int nt = 0; nt < 4; nt++) {
                unsigned bb0 = W2s[(k0 + tig) * WS_LD + nq * 32 + nt * 8 + g];
                unsigned bb1 = W2s[(k0 + tig + 4) * WS_LD + nq * 32 + nt * 8 + g];
                mma_tf32(c[0][nt], a[0][0], a[0][1], a[0][2], a[0][3], bb0, bb1);
                mma_tf32(c[1][nt], a[1][0], a[1][1], a[1][2], a[1][3], bb0, bb1);
            }
        }
        __syncthreads();

        // epilogue 2: relu(c + b2) -> As as fp32
#pragma unroll
        for (int m = 0; m < 2; m++)
#pragma unroll
            for (int nt = 0; nt < 4; nt++) {
                int cc = nq * 32 + nt * 8 + tig * 2;
                float bb0 = __ldg(b2 + cc), bb1v = __ldg(b2 + cc + 1);
                int r0l = mi * 32 + m * 16 + g;
                float v00 = fmaxf(c[m][nt][0] + bb0, 0.f);
                float v01 = fmaxf(c[m][nt][1] + bb1v, 0.f);
                float v10 = fmaxf(c[m][nt][2] + bb0, 0.f);
                float v11 = fmaxf(c[m][nt][3] + bb1v, 0.f);
                *(float2*)(Asf + r0l * AS_LD + cc) = make_float2(v00, v01);
                *(float2*)(Asf + (r0l + 8) * AS_LD + cc) = make_float2(v10, v11);
            }
        __syncthreads();

        // coalesced store of h2 (pre-BN) into out
        for (int i = t; i < 128 * 32; i += 512) {
            int r = i >> 5, c4 = i & 31;
            if (row0 + r < M)
                *(float4*)(out + (size_t)(row0 + r) * DIM + c4 * 4) =
                    *(const float4*)(Asf + r * AS_LD + c4 * 4);
        }

        // BN partials accumulated in registers across tiles
#pragma unroll 4
        for (int r = quarter * 32; r < quarter * 32 + 32; r++) {
            if (row0 + r < M) {
                float v = Asf[r * AS_LD + col];
                bns += v;
                bnss += v * v;
            }
        }
    }

    atomicAdd(&g_sum[col], bns);
    atomicAdd(&g_sumsq[col], bnss);
}

// K7: finalize BN stats -> scale/shift
__global__ void k_bnstats(const float* __restrict__ gamma, const float* __restrict__ beta, int n) {
    int c = threadIdx.x;
    if (c < DIM) {
        float inv = 1.f / (float)n;
        float mean = g_sum[c] * inv;
        float var = fmaxf(g_sumsq[c] * inv - mean * mean, 0.f);
        float sc = gamma[c] * rsqrtf(var + 1e-5f);
        g_scale[c] = sc;
        g_shift[c] = beta[c] - mean * sc;
    }
}

// K8: in-place BN apply (float4)
__global__ void k_apply(float* __restrict__ out, int total4) {
    int i = blockIdx.x * blockDim.x + threadIdx.x;
    if (i >= total4) return;
    int c4 = (i & 31) * 4;  // DIM/4 == 32
    float4 v = ((float4*)out)[i];
    float4 sc = *(const float4*)(g_scale + c4);
    float4 sh = *(const float4*)(g_shift + c4);
    v.x = v.x * sc.x + sh.x;
    v.y = v.y * sc.y + sh.y;
    v.z = v.z * sc.z + sh.z;
    v.w = v.w * sc.w + sh.w;
    ((float4*)out)[i] = v;
}

extern "C" void kernel_launch(void* const* d_in, const int* in_sizes, int n_in,
                              void* d_out, int out_size) {
    const float* feat = (const float*)d_in[0];
    const int* ei = (const int*)d_in[1];  // int32 (JAX x64 disabled)
    const float* w1 = (const float*)d_in[2];
    const float* b1 = (const float*)d_in[3];
    const float* w2 = (const float*)d_in[4];
    const float* b2 = (const float*)d_in[5];
    const float* gamma = (const float*)d_in[6];
    const float* beta = (const float*)d_in[7];
    float* out = (float*)d_out;

    int n = in_sizes[0] / DIM;   // 100000
    int e = in_sizes[1] / 2;     // 400000
    int nb1 = (n + 2047) / 2048; // 49
    int ntiles = (n + 127) / 128;

    int sms = 0;
    cudaDeviceGetAttribute(&sms, cudaDevAttrMultiProcessorCount, 0);
    if (sms <= 0) sms = 148;
    int grid = sms < ntiles ? sms : ntiles;

    cudaFuncSetAttribute(k_gemm, cudaFuncAttributeMaxDynamicSharedMemorySize, SMEM_BYTES);

    k_prep<<<(n + 255) / 256, 256>>>(w1, w2, n);
    k_hist<<<(e + 255) / 256, 256>>>(ei, e, n);
    k_scan1<<<nb1, 512>>>(n);
    k_scan2<<<1, 32>>>(nb1);
    k_scan3<<<(n + 255) / 256, 256>>>(n);
    k_scatter<<<(e + 255) / 256, 256>>>(ei, e, n);
    k_gemm<<<grid, 512, SMEM_BYTES>>>(feat, b1, b2, out, n, ntiles);
    k_bnstats<<<1, 128>>>(gamma, beta, n);
    int total4 = n * DIM / 4;
    k_apply<<<(total4 + 255) / 256, 256>>>(out, total4);
}

// round 6
// speedup vs baseline: 1.4850x; 1.4850x over previous
#include <cuda_runtime.h>
#include <stdint.h>

#define N_NODES_MAX 100000
#define N_EDGES_MAX 400000
#define DIM 128
#define AS_LD 132
#define WS_LD 136
#define MLP_SMEM_WORDS (128 * AS_LD + 2 * 128 * WS_LD)
#define MLP_SMEM_BYTES (MLP_SMEM_WORDS * 4)

// ---------------- scratch (device globals; no allocation allowed) ----------
__device__ int   g_deg[N_NODES_MAX];
__device__ int   g_off[N_NODES_MAX];
__device__ int   g_cur[N_NODES_MAX];
__device__ int   g_srcs[N_EDGES_MAX];
__device__ int   g_bsum[256];
__device__ float g_h[(size_t)N_NODES_MAX * DIM];
__device__ float g_sum[DIM];
__device__ float g_sumsq[DIM];
__device__ unsigned g_w1t[128 * WS_LD];
__device__ unsigned g_w2t[128 * WS_LD];
__device__ unsigned g_bar_build;
__device__ unsigned g_bar_mlp;

__device__ __forceinline__ void grid_sync(unsigned* cnt, int grid) {
    __syncthreads();
    if (threadIdx.x == 0) {
        __threadfence();
        unsigned old = atomicAdd(cnt, 1u);
        unsigned target = (old / (unsigned)grid + 1u) * (unsigned)grid;
        while (*(volatile unsigned*)cnt < target) __nanosleep(32);
        __threadfence();
    }
    __syncthreads();
}

__device__ __forceinline__ unsigned f2tf32(float f) {
    unsigned u;
    asm("cvt.rna.tf32.f32 %0, %1;" : "=r"(u) : "f"(f));
    return u;
}

__device__ __forceinline__ void mma_tf32(float c[4], unsigned a0, unsigned a1,
                                         unsigned a2, unsigned a3,
                                         unsigned b0, unsigned b1) {
    asm volatile(
        "mma.sync.aligned.m16n8k8.row.col.f32.tf32.tf32.f32 "
        "{%0,%1,%2,%3}, {%4,%5,%6,%7}, {%8,%9}, {%0,%1,%2,%3};"
        : "+f"(c[0]), "+f"(c[1]), "+f"(c[2]), "+f"(c[3])
        : "r"(a0), "r"(a1), "r"(a2), "r"(a3), "r"(b0), "r"(b1));
}

// =================== K1: persistent CSR builder ===================
// phases: zero+weights | hist | chunk scan | top scan | fixup | scatter
__global__ void __launch_bounds__(1024, 1)
k_build(const int* __restrict__ ei,
        const float* __restrict__ w1, const float* __restrict__ w2,
        int e, int n, int grid) {
    const int t = threadIdx.x;
    const int bid = blockIdx.x;
    const int gtid = bid * 1024 + t;
    const int gstride = grid * 1024;

    // ---- phase 0: zero counters/accumulators, transpose weights to tf32 ----
    for (int i = gtid; i < n; i += gstride) g_deg[i] = 0;
    if (gtid < DIM) { g_sum[gtid] = 0.f; g_sumsq[gtid] = 0.f; }
    for (int i = gtid; i < 128 * WS_LD; i += gstride) {
        int k = i / WS_LD, c = i % WS_LD;
        unsigned v1 = 0, v2 = 0;
        if (c < 128) { v1 = f2tf32(w1[c * 128 + k]); v2 = f2tf32(w2[c * 128 + k]); }
        g_w1t[i] = v1;
        g_w2t[i] = v2;
    }
    grid_sync(&g_bar_build, grid);

    // ---- phase 1: in-degree histogram ----
    for (int i = gtid; i < e; i += gstride) {
        int d = __ldg(ei + e + i);
        if ((unsigned)d < (unsigned)n) atomicAdd(&g_deg[d], 1);
    }
    grid_sync(&g_bar_build, grid);

    // ---- phase 2: per-CTA chunk exclusive scan (chunk <= 4096) ----
    __shared__ int wsum[32];
    const int chunk = (n + grid - 1) / grid;
    const int start = bid * chunk;
    int cnt = n - start;
    if (cnt < 0) cnt = 0;
    if (cnt > chunk) cnt = chunk;

    const int base = t * 4;
    int v0 = 0, v1 = 0, v2 = 0, v3 = 0;
    if (base + 0 < cnt) v0 = g_deg[start + base + 0];
    if (base + 1 < cnt) v1 = g_deg[start + base + 1];
    if (base + 2 < cnt) v2 = g_deg[start + base + 2];
    if (base + 3 < cnt) v3 = g_deg[start + base + 3];
    int tsum = v0 + v1 + v2 + v3;
    int lane = t & 31, w = t >> 5;
    int incl = tsum;
#pragma unroll
    for (int o = 1; o < 32; o <<= 1) {
        int x = __shfl_up_sync(~0u, incl, o);
        if (lane >= o) incl += x;
    }
    if (lane == 31) wsum[w] = incl;
    __syncthreads();
    if (t < 32) {
        int s = wsum[t];
        int i2 = s;
#pragma unroll
        for (int o = 1; o < 32; o <<= 1) {
            int x = __shfl_up_sync(~0u, i2, o);
            if (t >= o) i2 += x;
        }
        wsum[t] = i2 - s;
        if (t == 31) g_bsum[bid] = i2;
    }
    __syncthreads();
    int run = incl - tsum + wsum[w];
    if (base + 0 < cnt) { g_off[start + base + 0] = run; run += v0; }
    if (base + 1 < cnt) { g_off[start + base + 1] = run; run += v1; }
    if (base + 2 < cnt) { g_off[start + base + 2] = run; run += v2; }
    if (base + 3 < cnt) { g_off[start + base + 3] = run; }
    grid_sync(&g_bar_build, grid);

    // ---- phase 3: CTA0 warp scans the block totals (grid <= 256) ----
    if (bid == 0 && t < 32) {
        int per = (grid + 31) >> 5;  // <= 8
        int loc[8];
        int s = 0;
#pragma unroll 8
        for (int j = 0; j < 8; j++) {
            int idx = t * per + j;
            int v = (j < per && idx < grid) ? g_bsum[idx] : 0;
            loc[j] = v;
            s += v;
        }
        int i2 = s;
#pragma unroll
        for (int o = 1; o < 32; o <<= 1) {
            int x = __shfl_up_sync(~0u, i2, o);
            if (t >= o) i2 += x;
        }
        int r2 = i2 - s;
#pragma unroll 8
        for (int j = 0; j < 8; j++) {
            int idx = t * per + j;
            if (j < per && idx < grid) { g_bsum[idx] = r2; r2 += loc[j]; }
        }
    }
    grid_sync(&g_bar_build, grid);

    // ---- phase 4: add block offset, init cursors ----
    {
        int add = g_bsum[bid];
        for (int i = t; i < cnt; i += 1024) {
            int o = g_off[start + i] + add;
            g_off[start + i] = o;
            g_cur[start + i] = o;
        }
    }
    grid_sync(&g_bar_build, grid);

    // ---- phase 5: scatter src indices into CSR ----
    for (int i = gtid; i < e; i += gstride) {
        int d = ei[e + i];
        int s = ei[i];
        if ((unsigned)d < (unsigned)n && (unsigned)s < (unsigned)n) {
            int p = atomicAdd(&g_cur[d], 1);
            if ((unsigned)p < (unsigned)N_EDGES_MAX) g_srcs[p] = s;
        }
    }
}

// =================== K2: per-node gather-sum (unchanged, proven) ===========
__global__ void k_agg(const float* __restrict__ x, int n) {
    int warp = (blockIdx.x * blockDim.x + threadIdx.x) >> 5;
    int lane = threadIdx.x & 31;
    if (warp >= n) return;
    float4 acc = ((const float4*)(x + (size_t)warp * DIM))[lane];
    int e = g_off[warp];
    int end = e + g_deg[warp];
    for (; e + 4 <= end; e += 4) {
        int s0 = g_srcs[e], s1 = g_srcs[e + 1], s2 = g_srcs[e + 2], s3 = g_srcs[e + 3];
        float4 v0 = ((const float4*)(x + (size_t)s0 * DIM))[lane];
        float4 v1 = ((const float4*)(x + (size_t)s1 * DIM))[lane];
        float4 v2 = ((const float4*)(x + (size_t)s2 * DIM))[lane];
        float4 v3 = ((const float4*)(x + (size_t)s3 * DIM))[lane];
        acc.x += v0.x + v1.x + v2.x + v3.x;
        acc.y += v0.y + v1.y + v2.y + v3.y;
        acc.z += v0.z + v1.z + v2.z + v3.z;
        acc.w += v0.w + v1.w + v2.w + v3.w;
    }
    for (; e < end; e++) {
        float4 v = ((const float4*)(x + (size_t)g_srcs[e] * DIM))[lane];
        acc.x += v.x; acc.y += v.y; acc.z += v.z; acc.w += v.w;
    }
    ((float4*)(g_h + (size_t)warp * DIM))[lane] = acc;
}

// =================== K3: persistent MLP + BN (stats, sync, apply) ==========
__global__ void __launch_bounds__(512, 1)
k_mlp(const float* __restrict__ b1, const float* __restrict__ b2,
      const float* __restrict__ gamma, const float* __restrict__ beta,
      float* __restrict__ out, int M, int ntiles, int grid) {
    extern __shared__ unsigned sm[];
    unsigned* As = sm;                       // 128 x AS_LD
    unsigned* W1s = sm + 128 * AS_LD;        // 128 x WS_LD
    unsigned* W2s = W1s + 128 * WS_LD;       // 128 x WS_LD
    float* Asf = (float*)As;

    const int t = threadIdx.x;
    const int lane = t & 31, wid = t >> 5;
    const int g = lane >> 2, tig = lane & 3;
    const int mi = wid & 3;   // 4 row-blocks of 32
    const int nq = wid >> 2;  // 4 col-blocks of 32
    const int col = t & 127, quarter = t >> 7;

    // one-time: both weight matrices resident in SMEM
    for (int i = t; i < 128 * WS_LD; i += 512) {
        W1s[i] = g_w1t[i];
        W2s[i] = g_w2t[i];
    }

    float bns = 0.f, bnss = 0.f;

    for (int tile = blockIdx.x; tile < ntiles; tile += grid) {
        const int row0 = tile * 128;
        __syncthreads();  // protect As reuse across iterations

        // stage A tile from g_h (tf32-rounded)
        for (int i = t; i < 128 * 32; i += 512) {
            int r = i >> 5, c4 = i & 31;
            float4 v = make_float4(0.f, 0.f, 0.f, 0.f);
            if (row0 + r < M) v = *(const float4*)(g_h + (size_t)(row0 + r) * DIM + c4 * 4);
            uint4 u = make_uint4(f2tf32(v.x), f2tf32(v.y), f2tf32(v.z), f2tf32(v.w));
            *(uint4*)(As + r * AS_LD + c4 * 4) = u;
        }
        __syncthreads();

        float c[2][4][4];

        // ---------- layer 1 ----------
#pragma unroll
        for (int m = 0; m < 2; m++)
#pragma unroll
            for (int nt = 0; nt < 4; nt++)
#pragma unroll
                for (int j = 0; j < 4; j++) c[m][nt][j] = 0.f;

#pragma unroll 4
        for (int ks = 0; ks < 16; ks++) {
            int k0 = ks * 8;
            unsigned a[2][4];
#pragma unroll
            for (int m = 0; m < 2; m++) {
                int rb = mi * 32 + m * 16;
                a[m][0] = As[(rb + g) * AS_LD + k0 + tig];
                a[m][1] = As[(rb + g + 8) * AS_LD + k0 + tig];
                a[m][2] = As[(rb + g) * AS_LD + k0 + tig + 4];
                a[m][3] = As[(rb + g + 8) * AS_LD + k0 + tig + 4];
            }
#pragma unroll
            for (int nt = 0; nt < 4; nt++) {
                unsigned bb0 = W1s[(k0 + tig) * WS_LD + nq * 32 + nt * 8 + g];
                unsigned bb1 = W1s[(k0 + tig + 4) * WS_LD + nq * 32 + nt * 8 + g];
                mma_tf32(c[0][nt], a[0][0], a[0][1], a[0][2], a[0][3], bb0, bb1);
                mma_tf32(c[1][nt], a[1][0], a[1][1], a[1][2], a[1][3], bb0, bb1);
            }
        }
        __syncthreads();

        // epilogue 1: relu(c + b1) -> As (tf32)
#pragma unroll
        for (int m = 0; m < 2; m++)
#pragma unroll
            for (int nt = 0; nt < 4; nt++) {
                int cc = nq * 32 + nt * 8 + tig * 2;
                float bb0 = __ldg(b1 + cc), bb1v = __ldg(b1 + cc + 1);
                int r0l = mi * 32 + m * 16 + g;
                float v00 = fmaxf(c[m][nt][0] + bb0, 0.f);
                float v01 = fmaxf(c[m][nt][1] + bb1v, 0.f);
                float v10 = fmaxf(c[m][nt][2] + bb0, 0.f);
                float v11 = fmaxf(c[m][nt][3] + bb1v, 0.f);
                *(uint2*)(As + r0l * AS_LD + cc) = make_uint2(f2tf32(v00), f2tf32(v01));
                *(uint2*)(As + (r0l + 8) * AS_LD + cc) = make_uint2(f2tf32(v10), f2tf32(v11));
            }
        __syncthreads();

        // ---------- layer 2 ----------
#pragma unroll
        for (int m = 0; m < 2; m++)
#pragma unroll
            for (int nt = 0; nt < 4; nt++)
#pragma unroll
                for (int j = 0; j < 4; j++) c[m][nt][j] = 0.f;

#pragma unroll 4
        for (int ks = 0; ks < 16; ks++) {
            int k0 = ks * 8;
            unsigned a[2][4];
#pragma unroll
            for (int m = 0; m < 2; m++) {
                int rb = mi * 32 + m * 16;
                a[m][0] = As[(rb + g) * AS_LD + k0 + tig];
                a[m][1] = As[(rb + g + 8) * AS_LD + k0 + tig];
                a[m][2] = As[(rb + g) * AS_LD + k0 + tig + 4];
                a[m][3] = As[(rb + g + 8) * AS_LD + k0 + tig + 4];
            }
#pragma unroll
            for (int nt = 0; nt < 4; nt++) {
                unsigned bb0 = W2s[(k0 + tig) * WS_LD + nq * 32 + nt * 8 + g];
                unsigned bb1 = W2s[(k0 + tig + 4) * WS_LD + nq * 32 + nt * 8 + g];
                mma_tf32(c[0][nt], a[0][0], a[0][1], a[0][2], a[0][3], bb0, bb1);
                mma_tf32(c[1][nt], a[1][0], a[1][1], a[1][2], a[1][3], bb0, bb1);
            }
        }
        __syncthreads();

        // epilogue 2: relu(c + b2) -> As as fp32
#pragma unroll
        for (int m = 0; m < 2; m++)
#pragma unroll
            for (int nt = 0; nt < 4; nt++) {
                int cc = nq * 32 + nt * 8 + tig * 2;
                float bb0 = __ldg(b2 + cc), bb1v = __ldg(b2 + cc + 1);
                int r0l = mi * 32 + m * 16 + g;
                float v00 = fmaxf(c[m][nt][0] + bb0, 0.f);
                float v01 = fmaxf(c[m][nt][1] + bb1v, 0.f);
                float v10 = fmaxf(c[m][nt][2] + bb0, 0.f);
                float v11 = fmaxf(c[m][nt][3] + bb1v, 0.f);
                *(float2*)(Asf + r0l * AS_LD + cc) = make_float2(v00, v01);
                *(float2*)(Asf + (r0l + 8) * AS_LD + cc) = make_float2(v10, v11);
            }
        __syncthreads();

        // coalesced store of h2 (pre-BN)
        for (int i = t; i < 128 * 32; i += 512) {
            int r = i >> 5, c4 = i & 31;
            if (row0 + r < M)
                *(float4*)(out + (size_t)(row0 + r) * DIM + c4 * 4) =
                    *(const float4*)(Asf + r * AS_LD + c4 * 4);
        }

        // BN partials accumulated in registers across tiles
#pragma unroll 4
        for (int r = quarter * 32; r < quarter * 32 + 32; r++) {
            if (row0 + r < M) {
                float v = Asf[r * AS_LD + col];
                bns += v;
                bnss += v * v;
            }
        }
    }

    atomicAdd(&g_sum[col], bns);
    atomicAdd(&g_sumsq[col], bnss);

    grid_sync(&g_bar_mlp, grid);

    // each CTA computes scale/shift locally into SMEM (reuse As region)
    if (t < DIM) {
        float inv = 1.f / (float)M;
        float mean = g_sum[t] * inv;
        float var = fmaxf(g_sumsq[t] * inv - mean * mean, 0.f);
        float sc = gamma[t] * rsqrtf(var + 1e-5f);
        Asf[t] = sc;
        Asf[128 + t] = beta[t] - mean * sc;
    }
    __syncthreads();

    // apply BN in-place over out (float4)
    int total4 = M * (DIM / 4);
    for (int i = blockIdx.x * 512 + t; i < total4; i += grid * 512) {
        int c4 = (i & 31) * 4;
        float4 v = ((float4*)out)[i];
        float4 sc = *(const float4*)(Asf + c4);
        float4 sh = *(const float4*)(Asf + 128 + c4);
        v.x = v.x * sc.x + sh.x;
        v.y = v.y * sc.y + sh.y;
        v.z = v.z * sc.z + sh.z;
        v.w = v.w * sc.w + sh.w;
        ((float4*)out)[i] = v;
    }
}

extern "C" void kernel_launch(void* const* d_in, const int* in_sizes, int n_in,
                              void* d_out, int out_size) {
    const float* feat = (const float*)d_in[0];
    const int* ei = (const int*)d_in[1];  // int32 (JAX x64 disabled)
    const float* w1 = (const float*)d_in[2];
    const float* b1 = (const float*)d_in[3];
    const float* w2 = (const float*)d_in[4];
    const float* b2 = (const float*)d_in[5];
    const float* gamma = (const float*)d_in[6];
    const float* beta = (const float*)d_in[7];
    float* out = (float*)d_out;

    int n = in_sizes[0] / DIM;   // 100000
    int e = in_sizes[1] / 2;     // 400000
    int ntiles = (n + 127) / 128;

    int sms = 0;
    cudaDeviceGetAttribute(&sms, cudaDevAttrMultiProcessorCount, 0);
    if (sms <= 0) sms = 148;
    if (sms > 256) sms = 256;
    int gm = sms < ntiles ? sms : ntiles;

    cudaFuncSetAttribute(k_mlp, cudaFuncAttributeMaxDynamicSharedMemorySize, MLP_SMEM_BYTES);

    k_build<<<sms, 1024>>>(ei, w1, w2, e, n, sms);
    k_agg<<<(n + 7) / 8, 256>>>(feat, n);
    k_mlp<<<gm, 512, MLP_SMEM_BYTES>>>(b1, b2, gamma, beta, out, n, ntiles, gm);
}